// round 9
// baseline (speedup 1.0000x reference)
#include <cuda_runtime.h>
#include <cuda_fp16.h>
#include <cstdint>

// Problem constants (fixed shapes)
#define Tn 100
#define Bn 4096
#define Cn 512
#define Dn 512
#define NW 16                    // 512 bits / 32 = mask words per (t,b)
#define NBLK 148                 // persistent blocks (1 per SM on B200)
#define NASSIGN 2048             // Bn/2 assignments, 2 batches each

// ---------------- scratch (static device globals; no allocation) ------------
__device__ uint32_t g_mask[Tn*Bn*NW];   // 26.2 MB packed dropout masks (for K4)
__device__ __half   g_Wh[Dn*Cn];        // W pre-converted to fp16 (rn)
__device__ float    g_invn[Bn*Tn];      // 1/|y_tb|
__device__ float    g_u[Bn*Cn];         // u_b[c] = 2 x_bc * sum_t m/n
__device__ float    g_sigma[Bn];        // sum_t 1/n
__device__ float    g_S[Bn*Dn];         // sum_t f_t  (unnormalized mean dir)
__device__ float    g_v[Bn*Cn];         // v_b = W^T S_b
__device__ float    g_sinv[Bn];         // 1/|S_b|
__device__ float    g_c0[Bn];           // b^T S_b

// ---------------- threefry2x32 (JAX-exact, key = (0, 42)) -------------------
__device__ __forceinline__ void tf_round4(uint32_t& x0, uint32_t& x1,
                                          int a, int b, int c, int d) {
  x0 += x1; x1 = __funnelshift_l(x1, x1, a); x1 ^= x0;
  x0 += x1; x1 = __funnelshift_l(x1, x1, b); x1 ^= x0;
  x0 += x1; x1 = __funnelshift_l(x1, x1, c); x1 ^= x0;
  x0 += x1; x1 = __funnelshift_l(x1, x1, d); x1 ^= x0;
}

__device__ __forceinline__ uint2 threefry2x32(uint32_t x0, uint32_t x1) {
  const uint32_t k0 = 0u, k1 = 42u;
  const uint32_t k2 = k0 ^ k1 ^ 0x1BD11BDAu;
  x0 += k0; x1 += k1;
  tf_round4(x0, x1, 13, 15, 26, 6);   x0 += k1; x1 += k2 + 1u;
  tf_round4(x0, x1, 17, 29, 16, 24);  x0 += k2; x1 += k0 + 2u;
  tf_round4(x0, x1, 13, 15, 26, 6);   x0 += k0; x1 += k1 + 3u;
  tf_round4(x0, x1, 17, 29, 16, 24);  x0 += k1; x1 += k2 + 4u;
  tf_round4(x0, x1, 13, 15, 26, 6);   x0 += k2; x1 += k0 + 5u;
  return make_uint2(x0, x1);
}

// K0b: pre-convert W to fp16 (rn) once.
__global__ void k0b_halfW(const float* __restrict__ W) {
  int i = blockIdx.x * blockDim.x + threadIdx.x;
  g_Wh[i] = __float2half(W[i]);
}

// ---------------- fused K0+K1: persistent fp16 TC row-norm GEMM -------------
__device__ __forceinline__ void mma_f16(float (&d)[4],
                                        uint32_t a0, uint32_t a1,
                                        uint32_t a2, uint32_t a3,
                                        uint32_t b0, uint32_t b1) {
  asm volatile(
      "mma.sync.aligned.m16n8k16.row.col.f32.f16.f16.f32 "
      "{%0,%1,%2,%3}, {%4,%5,%6,%7}, {%8,%9}, {%0,%1,%2,%3};"
      : "+f"(d[0]), "+f"(d[1]), "+f"(d[2]), "+f"(d[3])
      : "r"(a0), "r"(a1), "r"(a2), "r"(a3), "r"(b0), "r"(b1));
}

__device__ __forceinline__ void cpasync16(uint32_t smem_addr, const void* g) {
  asm volatile("cp.async.cg.shared.global [%0], [%1], 16;"
               :: "r"(smem_addr), "l"(g));
}

#define WPADH 72     // W smem row stride in halfs (byte stride 144)
#define MPAD 17      // mask smem row stride (words)
#define NCOLS 224    // 2 b x 112 padded t
#define WBUFH (128 * WPADH)         // halfs per W stage buffer
#define MBUFW (NCOLS * MPAD)        // words per mask buffer (3808)

// smem bytes: W 2*WBUFH*2 | xh 512*4 | mask2 2*MBUFW*4 | norm2 224*4
#define OFF_XH   (2 * WBUFH * 2)
#define OFF_MASK (OFF_XH + 512 * 4)
#define OFF_NORM (OFF_MASK + 2 * MBUFW * 4)
#define K1_SMEM_BYTES (OFF_NORM + NCOLS * 4)

extern __shared__ char k1s[];

// Generate one 32-bit mask word (ballot across the warp) for assignment-local
// word index m in [0,3200): bs = m/1600, t = (m%1600)/16, w = m%16.
// Writes swizzle-free into mS[(bs*112+t)*MPAD + w] and to g_mask.
__device__ __forceinline__ void gen_word(uint32_t* mS, int m, int nb0, int lane) {
  int bs = (m >= 1600) ? 1 : 0;
  int r = m - bs * 1600;
  int t = r >> 4, w = r & 15;
  uint32_t wg = ((uint32_t)(t * Bn + nb0 + bs) << 4) + (uint32_t)w;
  uint32_t e = (wg << 5) + (uint32_t)lane;
  uint2 o = threefry2x32(0u, e);
  uint32_t keep = (((o.x ^ o.y) >> 31) & 1u) ^ 1u;
  uint32_t word = __ballot_sync(0xFFFFFFFFu, keep != 0u);
  if (lane == 0) {
    mS[(bs * 112 + t) * MPAD + w] = word;
    g_mask[wg] = word;
  }
}

__global__ __launch_bounds__(256) void k01_fused(
    const float* __restrict__ x, const float* __restrict__ bias) {
  __half* Wbuf = (__half*)k1s;
  uint32_t* xh = (uint32_t*)(k1s + OFF_XH);
  uint32_t* mask2 = (uint32_t*)(k1s + OFF_MASK);
  float* norm2 = (float*)(k1s + OFF_NORM);

  const int tid = threadIdx.x;
  const int lane = tid & 31, wid = tid >> 5;
  const int warp_m = wid & 1;          // 2 m-warps (64 d each)
  const int warp_n = wid >> 1;         // 4 n-warps (56 cols each)
  const int gID = lane >> 2, tig = lane & 3;
  const int n0 = warp_n * 56;
  const int bsel = warp_n >> 1;        // this warp's batch for xh

  // zero both mask buffers once (covers the t in [100,112) pad rows forever)
  for (int i = tid; i < 2 * MBUFW; i += 256) mask2[i] = 0u;
  __syncthreads();

  // un-overlapped gen for this block's first assignment -> buffer 0
  {
    const int fb0 = blockIdx.x * 2;
    for (int m = wid; m < 3200; m += 8) gen_word(mask2, m, fb0, lane);
  }

  int curbuf = 0;
  for (int a = blockIdx.x; a < NASSIGN; a += NBLK, curbuf ^= 1) {
    uint32_t* mcur = mask2 + curbuf * MBUFW;
    uint32_t* mnxt = mask2 + (curbuf ^ 1) * MBUFW;
    const int b0 = a * 2;
    const int an = a + NBLK;
    const bool hasnext = an < NASSIGN;
    const int nb0 = an * 2;

    __syncthreads();  // prior epilogue reads + prologue-gen STS visible

    // xh for this assignment; norm2 reset
    for (int i = tid; i < 512; i += 256) {
      int bs = i >> 8, c2 = i & 255;
      float lo = 2.0f * x[(b0 + bs) * Cn + 2 * c2];
      float hi = 2.0f * x[(b0 + bs) * Cn + 2 * c2 + 1];
      __half2 h = __floats2half2_rn(lo, hi);
      xh[i] = *reinterpret_cast<uint32_t*>(&h);
    }
    if (tid < NCOLS) norm2[tid] = 0.0f;

    // W stage-0 prologue
    {
      __half* Wb = Wbuf;
      const __half* Wg = g_Wh;
#pragma unroll
      for (int r = 0; r < 4; r++) {
        int l = tid + r * 256;
        int d = l >> 3, ch = l & 7;
        cpasync16((uint32_t)__cvta_generic_to_shared(Wb + d * WPADH + ch * 8),
                  Wg + d * Cn + ch * 8);
      }
      asm volatile("cp.async.commit_group;");
    }

    float acc[4][7][4];
#pragma unroll
    for (int mt = 0; mt < 4; mt++)
#pragma unroll
      for (int nt = 0; nt < 7; nt++)
#pragma unroll
        for (int r = 0; r < 4; r++) acc[mt][nt][r] = 0.0f;
    float ns0[7], ns1[7];
#pragma unroll
    for (int nt = 0; nt < 7; nt++) { ns0[nt] = 0.0f; ns1[nt] = 0.0f; }

#pragma unroll 1
    for (int s = 0; s < 32; s++) {
      const int kc = s & 7;
      if (s < 31) {
        int s1 = s + 1;
        __half* Wb = Wbuf + (s1 & 1) * WBUFH;
        const __half* Wg = g_Wh + ((s1 >> 3) * 128) * Cn + (s1 & 7) * 64;
#pragma unroll
        for (int r = 0; r < 4; r++) {
          int l = tid + r * 256;
          int d = l >> 3, ch = l & 7;
          cpasync16((uint32_t)__cvta_generic_to_shared(Wb + d * WPADH + ch * 8),
                    Wg + d * Cn + ch * 8);
        }
        asm volatile("cp.async.commit_group;");
        asm volatile("cp.async.wait_group 1;");
      } else {
        asm volatile("cp.async.wait_group 0;");
      }
      __syncthreads();

      const __half* Wb = Wbuf + (s & 1) * WBUFH;
      uint32_t mw0[7], mw1[7];
#pragma unroll
      for (int nt = 0; nt < 7; nt++) {
        int col = n0 + nt * 8 + gID;
        mw0[nt] = mcur[col * MPAD + kc * 2];
        mw1[nt] = mcur[col * MPAD + kc * 2 + 1];
      }

#pragma unroll
      for (int kt = 0; kt < 4; kt++) {   // k16 tiles within 64-c chunk
        uint32_t xp0 = xh[bsel * 256 + kc * 32 + kt * 8 + tig];
        uint32_t xp1 = xh[bsel * 256 + kc * 32 + kt * 8 + tig + 4];
        const __half* rp = Wb + (warp_m * 64 + gID) * WPADH + kt * 16 + tig * 2;
        uint32_t aF[4][4];
#pragma unroll
        for (int mt = 0; mt < 4; mt++) {
          aF[mt][0] = *reinterpret_cast<const uint32_t*>(rp + (mt * 16) * WPADH);
          aF[mt][1] = *reinterpret_cast<const uint32_t*>(rp + (mt * 16 + 8) * WPADH);
          aF[mt][2] = *reinterpret_cast<const uint32_t*>(rp + (mt * 16) * WPADH + 8);
          aF[mt][3] = *reinterpret_cast<const uint32_t*>(rp + (mt * 16 + 8) * WPADH + 8);
        }
        const int bit = ((kt & 1) << 4) + 2 * tig;
#pragma unroll
        for (int nt = 0; nt < 7; nt++) {
          uint32_t w = (kt < 2) ? mw0[nt] : mw1[nt];
          uint32_t sel0 = ((0u - ((w >> bit) & 1u)) & 0x0000FFFFu) |
                          ((0u - ((w >> (bit + 1)) & 1u)) & 0xFFFF0000u);
          uint32_t sel1 = ((0u - ((w >> (bit + 8)) & 1u)) & 0x0000FFFFu) |
                          ((0u - ((w >> (bit + 9)) & 1u)) & 0xFFFF0000u);
          uint32_t bf0 = xp0 & sel0;
          uint32_t bf1 = xp1 & sel1;
          mma_f16(acc[0][nt], aF[0][0], aF[0][1], aF[0][2], aF[0][3], bf0, bf1);
          mma_f16(acc[1][nt], aF[1][0], aF[1][1], aF[1][2], aF[1][3], bf0, bf1);
          mma_f16(acc[2][nt], aF[2][0], aF[2][1], aF[2][2], aF[2][3], bf0, bf1);
          mma_f16(acc[3][nt], aF[3][0], aF[3][1], aF[3][2], aF[3][3], bf0, bf1);
        }
      }

      // overlapped threefry: 1/32 of next assignment's masks while HMMAs drain
      if (hasnext) {
        const int cnt = (wid < 4) ? 13 : 12;
        const int mbase = s * 100 + wid;
#pragma unroll 1
        for (int j = 0; j < cnt; j++)
          gen_word(mnxt, mbase + 8 * j, nb0, lane);
      }

      // mi epilogue: fold y = acc + bias into register norm partials
      if (kc == 7) {
        const int mi = s >> 3;
        float blo[4], bhi[4];
#pragma unroll
        for (int mt = 0; mt < 4; mt++) {
          int dg = mi * 128 + warp_m * 64 + mt * 16 + gID;
          blo[mt] = bias[dg];
          bhi[mt] = bias[dg + 8];
        }
#pragma unroll
        for (int nt = 0; nt < 7; nt++) {
          float s0 = 0.0f, s1 = 0.0f;
#pragma unroll
          for (int mt = 0; mt < 4; mt++) {
            float y0 = acc[mt][nt][0] + blo[mt];
            float y1 = acc[mt][nt][1] + blo[mt];
            float y2 = acc[mt][nt][2] + bhi[mt];
            float y3 = acc[mt][nt][3] + bhi[mt];
            s0 += y0 * y0 + y2 * y2;
            s1 += y1 * y1 + y3 * y3;
            acc[mt][nt][0] = 0.0f; acc[mt][nt][1] = 0.0f;
            acc[mt][nt][2] = 0.0f; acc[mt][nt][3] = 0.0f;
          }
          ns0[nt] += s0;
          ns1[nt] += s1;
        }
      }
      __syncthreads();
    }

    // cross-gID reduce, then conflict-free smem atomic
#pragma unroll
    for (int nt = 0; nt < 7; nt++) {
#pragma unroll
      for (int off = 4; off < 32; off <<= 1) {
        ns0[nt] += __shfl_xor_sync(0xFFFFFFFFu, ns0[nt], off);
        ns1[nt] += __shfl_xor_sync(0xFFFFFFFFu, ns1[nt], off);
      }
    }
    if (lane < 4) {
#pragma unroll
      for (int nt = 0; nt < 7; nt++) {
        atomicAdd(&norm2[n0 + nt * 8 + 2 * tig], ns0[nt]);
        atomicAdd(&norm2[n0 + nt * 8 + 2 * tig + 1], ns1[nt]);
      }
    }
    __syncthreads();
    // invn (overwrite norm2 with invn for the fused-K2 pass)
    if (tid < NCOLS) {
      int bs = (tid >= 112) ? 1 : 0;
      int t = tid - bs * 112;
      float iv = rsqrtf(norm2[tid]);
      norm2[tid] = iv;
      if (t < Tn) g_invn[(b0 + bs) * Tn + t] = iv;
    }
    __syncthreads();

    // fused K2: sigma_b and u_b[c] = 2 x * sum_t m/n
    if (tid < 2) {
      float s = 0.0f;
      for (int t = 0; t < Tn; t++) s += norm2[tid * 112 + t];
      g_sigma[b0 + tid] = s;
    }
#pragma unroll
    for (int bs = 0; bs < 2; bs++) {
#pragma unroll
      for (int j = 0; j < 2; j++) {
        int c = tid + j * 256;
        int w = c >> 5, sh = c & 31;
        float s = 0.0f;
        for (int col = 0; col < 112; col++) {
          uint32_t mwv = mcur[(bs * 112 + col) * MPAD + w];
          if ((mwv >> sh) & 1u) s += norm2[bs * 112 + col];
        }
        g_u[(b0 + bs) * Cn + c] = 2.0f * x[(b0 + bs) * Cn + c] * s;
      }
    }
  }
}

// K3: small GEMMs. MODE 0: S = u * W^T + sigma*bias  ([B,C]x[C,D])
//                  MODE 1: v = S * W                 ([B,D]x[D,C])
template <int MODE>
__global__ void k3_gemm(const float* __restrict__ Wm,
                        const float* __restrict__ bias) {
  __shared__ float As[64][68];
  __shared__ float Bs[64][68];
  const float* A = (MODE == 0) ? g_u : g_S;
  float* outp = (MODE == 0) ? g_S : g_v;
  const int n0 = blockIdx.x * 64, m0 = blockIdx.y * 64;
  const int tid = threadIdx.x;                // 256
  const int nq = tid & 15, mq = tid >> 4;
  float acc[4][4] = {};
  for (int k0 = 0; k0 < 512; k0 += 64) {
    __syncthreads();
    for (int l = tid; l < 4096; l += 256) {
      int mm = l >> 6, kk = l & 63;
      As[kk][mm] = A[(m0 + mm) * 512 + k0 + kk];
    }
    if (MODE == 0) {
      for (int l = tid; l < 4096; l += 256) {
        int nn = l >> 6, kk = l & 63;
        Bs[kk][nn] = Wm[(n0 + nn) * 512 + k0 + kk];
      }
    } else {
      for (int l = tid; l < 4096; l += 256) {
        int kk = l >> 6, nn = l & 63;
        Bs[kk][nn] = Wm[(k0 + kk) * 512 + n0 + nn];
      }
    }
    __syncthreads();
#pragma unroll 8
    for (int kk = 0; kk < 64; kk++) {
      float4 av = *reinterpret_cast<const float4*>(&As[kk][mq * 4]);
      float4 bv = *reinterpret_cast<const float4*>(&Bs[kk][nq * 4]);
      float a[4] = {av.x, av.y, av.z, av.w};
      float bb[4] = {bv.x, bv.y, bv.z, bv.w};
#pragma unroll
      for (int i = 0; i < 4; i++)
#pragma unroll
        for (int j = 0; j < 4; j++) acc[i][j] = fmaf(a[i], bb[j], acc[i][j]);
    }
  }
#pragma unroll
  for (int i = 0; i < 4; i++) {
    int m = m0 + mq * 4 + i;
    float sg = (MODE == 0) ? g_sigma[m] : 0.0f;
#pragma unroll
    for (int j = 0; j < 4; j++) {
      int n = n0 + nq * 4 + j;
      float v = acc[i][j];
      if (MODE == 0) v += sg * bias[n];
      outp[m * 512 + n] = v;
    }
  }
}

// K3c: 1/|S_b| and b^T S_b
__global__ void k3c_reduce(const float* __restrict__ bias) {
  __shared__ float r1[128], r2[128];
  const int b = blockIdx.x, tid = threadIdx.x;  // 128
  float s1 = 0.0f, s2 = 0.0f;
  for (int d = tid; d < Dn; d += 128) {
    float v = g_S[b * Dn + d];
    s1 += v * v;
    s2 += bias[d] * v;
  }
  r1[tid] = s1; r2[tid] = s2;
  __syncthreads();
  for (int o = 64; o > 0; o >>= 1) {
    if (tid < o) { r1[tid] += r1[tid + o]; r2[tid] += r2[tid + o]; }
    __syncthreads();
  }
  if (tid == 0) { g_sinv[b] = rsqrtf(r1[0]); g_c0[b] = r2[0]; }
}

// K4: score_tb = (2 sum_c m*x*v + c0) * invn * sinv ; out = std over t (ddof=0)
__global__ void k4_scores(const float* __restrict__ x, float* __restrict__ out) {
  __shared__ float xv[Cn];
  __shared__ float sc[Tn];
  const int b = blockIdx.x, tid = threadIdx.x;  // 128
  for (int c = tid; c < Cn; c += 128)
    xv[c] = 2.0f * x[b * Cn + c] * g_v[b * Cn + c];
  __syncthreads();
  if (tid < Tn) {
    const int t = tid;
    const uint32_t* mw = &g_mask[(t * Bn + b) * NW];
    float s = 0.0f;
#pragma unroll
    for (int w = 0; w < NW; w++) {
      uint32_t m = mw[w];
      int base = w * 32;
#pragma unroll
      for (int k = 0; k < 32; k++)
        if (m & (1u << k)) s += xv[base + k];
    }
    sc[t] = (s + g_c0[b]) * g_invn[b * Tn + t] * g_sinv[b];
  }
  __syncthreads();
  if (tid == 0) {
    float m = 0.0f;
    for (int t = 0; t < Tn; t++) m += sc[t];
    m *= (1.0f / Tn);
    float v = 0.0f;
    for (int t = 0; t < Tn; t++) { float d = sc[t] - m; v += d * d; }
    v *= (1.0f / Tn);
    out[b] = sqrtf(v);
  }
}

extern "C" void kernel_launch(void* const* d_in, const int* in_sizes, int n_in,
                              void* d_out, int out_size) {
  const float* x    = (const float*)d_in[0];
  const float* W    = (const float*)d_in[1];
  const float* bias = (const float*)d_in[2];
  float* out = (float*)d_out;

  cudaFuncSetAttribute(k01_fused,
                       cudaFuncAttributeMaxDynamicSharedMemorySize,
                       K1_SMEM_BYTES);

  k0b_halfW<<<1024, 256>>>(W);                // fp16 W once
  k01_fused<<<NBLK, 256, K1_SMEM_BYTES>>>(x, bias);
  k3_gemm<0><<<dim3(8, 64), 256>>>(W, bias);  // S
  k3c_reduce<<<Bn, 128>>>(bias);              // |S|, b^T S
  k3_gemm<1><<<dim3(8, 64), 256>>>(W, bias);  // v = W^T S
  k4_scores<<<Bn, 128>>>(x, out);
}

// round 10
// speedup vs baseline: 1.6088x; 1.6088x over previous
#include <cuda_runtime.h>
#include <cuda_fp16.h>
#include <cstdint>

// Problem constants (fixed shapes)
#define Tn 100
#define Bn 4096
#define Cn 512
#define Dn 512
#define NW 16                    // 512 bits / 32 = mask words per (t,b)

// ---------------- scratch (static device globals; no allocation) ------------
__device__ uint32_t g_mask[Tn*Bn*NW];   // 26.2 MB packed dropout masks
__device__ __half   g_Wh[Dn*Cn];        // W fp16, row-major [d][c]
__device__ __half   g_WhT[Cn*Dn];       // W fp16 transposed [c][d]
__device__ float    g_invn[Bn*Tn];      // 1/|y_tb|
__device__ float    g_u[Bn*Cn];         // u_b[c] = 2 x_bc * sum_t m/n
__device__ float    g_sigma[Bn];        // sum_t 1/n
__device__ float    g_S[Bn*Dn];         // sum_t f_t  (unnormalized mean dir)
__device__ float    g_v[Bn*Cn];         // v_b = W^T S_b
__device__ float    g_sinv[Bn];         // 1/|S_b|
__device__ float    g_c0[Bn];           // b^T S_b

// ---------------- threefry2x32 (JAX-exact, key = (0, 42)) -------------------
__device__ __forceinline__ void tf_round4(uint32_t& x0, uint32_t& x1,
                                          int a, int b, int c, int d) {
  x0 += x1; x1 = __funnelshift_l(x1, x1, a); x1 ^= x0;
  x0 += x1; x1 = __funnelshift_l(x1, x1, b); x1 ^= x0;
  x0 += x1; x1 = __funnelshift_l(x1, x1, c); x1 ^= x0;
  x0 += x1; x1 = __funnelshift_l(x1, x1, d); x1 ^= x0;
}

__device__ __forceinline__ uint2 threefry2x32(uint32_t x0, uint32_t x1) {
  const uint32_t k0 = 0u, k1 = 42u;
  const uint32_t k2 = k0 ^ k1 ^ 0x1BD11BDAu;
  x0 += k0; x1 += k1;
  tf_round4(x0, x1, 13, 15, 26, 6);   x0 += k1; x1 += k2 + 1u;
  tf_round4(x0, x1, 17, 29, 16, 24);  x0 += k2; x1 += k0 + 2u;
  tf_round4(x0, x1, 13, 15, 26, 6);   x0 += k0; x1 += k1 + 3u;
  tf_round4(x0, x1, 17, 29, 16, 24);  x0 += k1; x1 += k2 + 4u;
  tf_round4(x0, x1, 13, 15, 26, 6);   x0 += k2; x1 += k0 + 5u;
  return make_uint2(x0, x1);
}

// K0: JAX threefry_partitionable 32-bit draws. bits(i) = out.x ^ out.y of
// threefry2x32(key=(0,42), ctr=(0, i)); keep <=> bit31 == 0.
__global__ void k0_masks() {
  uint32_t i = blockIdx.x * blockDim.x + threadIdx.x;   // element index
  uint2 o = threefry2x32(0u, i);
  uint32_t keep = (((o.x ^ o.y) >> 31) & 1u) ^ 1u;
  uint32_t word = __ballot_sync(0xFFFFFFFFu, keep != 0u);
  if ((threadIdx.x & 31u) == 0u) g_mask[i >> 5] = word;
}

// K0b: pre-convert W to fp16 (rn) once, plus transposed copy.
__global__ void k0b_halfW(const float* __restrict__ W) {
  int i = blockIdx.x * blockDim.x + threadIdx.x;
  int d = i >> 9, c = i & 511;
  __half h = __float2half(W[i]);
  g_Wh[i] = h;
  g_WhT[c * 512 + d] = h;
}

// ---------------- K1: fp16 tensor-core row-norm GEMM, NB=2 ------------------
__device__ __forceinline__ void mma_f16(float (&d)[4],
                                        uint32_t a0, uint32_t a1,
                                        uint32_t a2, uint32_t a3,
                                        uint32_t b0, uint32_t b1) {
  asm volatile(
      "mma.sync.aligned.m16n8k16.row.col.f32.f16.f16.f32 "
      "{%0,%1,%2,%3}, {%4,%5,%6,%7}, {%8,%9}, {%0,%1,%2,%3};"
      : "+f"(d[0]), "+f"(d[1]), "+f"(d[2]), "+f"(d[3])
      : "r"(a0), "r"(a1), "r"(a2), "r"(a3), "r"(b0), "r"(b1));
}

__device__ __forceinline__ void cpasync16(uint32_t smem_addr, const void* g) {
  asm volatile("cp.async.cg.shared.global [%0], [%1], 16;"
               :: "r"(smem_addr), "l"(g));
}

#define WPADH 72     // W smem row stride in halfs (byte stride 144)
#define MPAD 17      // mask smem row stride (words)
#define NCOLS 224    // 2 b x 112 padded t
#define WBUFH (128 * WPADH)   // halfs per W buffer

// dyn smem: Wbuf[2][WBUFH] halfs | xh[512] u32 | maskS[224*MPAD] u32 | norm2[224] f
extern __shared__ char k1smem[];

__global__ __launch_bounds__(256) void k1_norms_tc(
    const float* __restrict__ x, const float* __restrict__ bias) {
  __half* Wbuf = (__half*)k1smem;
  uint32_t* xh = (uint32_t*)(k1smem + 2 * WBUFH * 2);
  uint32_t* maskS = xh + 512;
  float* norm2 = (float*)(maskS + NCOLS * MPAD);

  const int b0 = blockIdx.x * 2;
  const int tid = threadIdx.x;
  const int lane = tid & 31, wid = tid >> 5;
  const int warp_m = wid & 1;          // 2 m-warps (64 d each)
  const int warp_n = wid >> 1;         // 4 n-warps (56 cols each)
  const int gID = lane >> 2, tig = lane & 3;
  const int n0 = warp_n * 56;
  const int bsel = warp_n >> 1;        // this warp's batch for xh

  // ---- block init ----
  for (int i = tid; i < 512; i += 256) {
    int bs = i >> 8, c2 = i & 255;
    float lo = 2.0f * x[(b0 + bs) * Cn + 2 * c2];
    float hi = 2.0f * x[(b0 + bs) * Cn + 2 * c2 + 1];
    __half2 h = __floats2half2_rn(lo, hi);
    xh[i] = *reinterpret_cast<uint32_t*>(&h);
  }
  for (int i = tid; i < NCOLS * NW; i += 256) {
    int col = i >> 4, w = i & 15;
    int bs = (col >= 112) ? 1 : 0;
    int t = col - bs * 112;
    maskS[col * MPAD + w] =
        (t < Tn) ? g_mask[(t * Bn + b0 + bs) * NW + w] : 0u;
  }
  if (tid < NCOLS) norm2[tid] = 0.0f;

  // ---- prologue: stage 0 ----
  {
    __half* Wb = Wbuf;
    const __half* Wg = g_Wh;  // mi=0, kc=0
#pragma unroll
    for (int r = 0; r < 4; r++) {
      int l = tid + r * 256;
      int d = l >> 3, ch = l & 7;
      cpasync16((uint32_t)__cvta_generic_to_shared(Wb + d * WPADH + ch * 8),
                Wg + d * Cn + ch * 8);
    }
    asm volatile("cp.async.commit_group;");
  }

  float acc[4][7][4];
#pragma unroll
  for (int mt = 0; mt < 4; mt++)
#pragma unroll
    for (int nt = 0; nt < 7; nt++)
#pragma unroll
      for (int r = 0; r < 4; r++) acc[mt][nt][r] = 0.0f;
  float ns0[7], ns1[7];
#pragma unroll
  for (int nt = 0; nt < 7; nt++) { ns0[nt] = 0.0f; ns1[nt] = 0.0f; }

#pragma unroll 1
  for (int s = 0; s < 32; s++) {
    const int kc = s & 7;
    // issue next stage
    if (s < 31) {
      int s1 = s + 1;
      __half* Wb = Wbuf + (s1 & 1) * WBUFH;
      const __half* Wg = g_Wh + ((s1 >> 3) * 128) * Cn + (s1 & 7) * 64;
#pragma unroll
      for (int r = 0; r < 4; r++) {
        int l = tid + r * 256;
        int d = l >> 3, ch = l & 7;
        cpasync16((uint32_t)__cvta_generic_to_shared(Wb + d * WPADH + ch * 8),
                  Wg + d * Cn + ch * 8);
      }
      asm volatile("cp.async.commit_group;");
      asm volatile("cp.async.wait_group 1;");
    } else {
      asm volatile("cp.async.wait_group 0;");
    }
    __syncthreads();

    const __half* Wb = Wbuf + (s & 1) * WBUFH;
    // per-stage mask words (LDS, padded stride -> conflict-free)
    uint32_t mw0[7], mw1[7];
#pragma unroll
    for (int nt = 0; nt < 7; nt++) {
      int col = n0 + nt * 8 + gID;
      mw0[nt] = maskS[col * MPAD + kc * 2];
      mw1[nt] = maskS[col * MPAD + kc * 2 + 1];
    }

#pragma unroll
    for (int kt = 0; kt < 4; kt++) {   // k16 tiles within 64-c chunk
      uint32_t xp0 = xh[bsel * 256 + kc * 32 + kt * 8 + tig];
      uint32_t xp1 = xh[bsel * 256 + kc * 32 + kt * 8 + tig + 4];
      const __half* rp = Wb + (warp_m * 64 + gID) * WPADH + kt * 16 + tig * 2;
      uint32_t a[4][4];
#pragma unroll
      for (int mt = 0; mt < 4; mt++) {
        a[mt][0] = *reinterpret_cast<const uint32_t*>(rp + (mt * 16) * WPADH);
        a[mt][1] = *reinterpret_cast<const uint32_t*>(rp + (mt * 16 + 8) * WPADH);
        a[mt][2] = *reinterpret_cast<const uint32_t*>(rp + (mt * 16) * WPADH + 8);
        a[mt][3] = *reinterpret_cast<const uint32_t*>(rp + (mt * 16 + 8) * WPADH + 8);
      }
      const int bit = ((kt & 1) << 4) + 2 * tig;
#pragma unroll
      for (int nt = 0; nt < 7; nt++) {
        uint32_t w = (kt < 2) ? mw0[nt] : mw1[nt];
        uint32_t sel0 = ((0u - ((w >> bit) & 1u)) & 0x0000FFFFu) |
                        ((0u - ((w >> (bit + 1)) & 1u)) & 0xFFFF0000u);
        uint32_t sel1 = ((0u - ((w >> (bit + 8)) & 1u)) & 0x0000FFFFu) |
                        ((0u - ((w >> (bit + 9)) & 1u)) & 0xFFFF0000u);
        uint32_t bf0 = xp0 & sel0;
        uint32_t bf1 = xp1 & sel1;
        mma_f16(acc[0][nt], a[0][0], a[0][1], a[0][2], a[0][3], bf0, bf1);
        mma_f16(acc[1][nt], a[1][0], a[1][1], a[1][2], a[1][3], bf0, bf1);
        mma_f16(acc[2][nt], a[2][0], a[2][1], a[2][2], a[2][3], bf0, bf1);
        mma_f16(acc[3][nt], a[3][0], a[3][1], a[3][2], a[3][3], bf0, bf1);
      }
    }

    // mi epilogue: fold y = acc + bias into register norm partials, reset acc
    if (kc == 7) {
      const int mi = s >> 3;
      float blo[4], bhi[4];
#pragma unroll
      for (int mt = 0; mt < 4; mt++) {
        int dg = mi * 128 + warp_m * 64 + mt * 16 + gID;
        blo[mt] = bias[dg];
        bhi[mt] = bias[dg + 8];
      }
#pragma unroll
      for (int nt = 0; nt < 7; nt++) {
        float s0 = 0.0f, s1 = 0.0f;
#pragma unroll
        for (int mt = 0; mt < 4; mt++) {
          float y0 = acc[mt][nt][0] + blo[mt];
          float y1 = acc[mt][nt][1] + blo[mt];
          float y2 = acc[mt][nt][2] + bhi[mt];
          float y3 = acc[mt][nt][3] + bhi[mt];
          s0 += y0 * y0 + y2 * y2;
          s1 += y1 * y1 + y3 * y3;
          acc[mt][nt][0] = 0.0f; acc[mt][nt][1] = 0.0f;
          acc[mt][nt][2] = 0.0f; acc[mt][nt][3] = 0.0f;
        }
        ns0[nt] += s0;
        ns1[nt] += s1;
      }
    }
    __syncthreads();
  }

  // cross-gID reduce (lanes sharing tig), then one conflict-free smem atomic
#pragma unroll
  for (int nt = 0; nt < 7; nt++) {
#pragma unroll
    for (int off = 4; off < 32; off <<= 1) {
      ns0[nt] += __shfl_xor_sync(0xFFFFFFFFu, ns0[nt], off);
      ns1[nt] += __shfl_xor_sync(0xFFFFFFFFu, ns1[nt], off);
    }
  }
  if (lane < 4) {
#pragma unroll
    for (int nt = 0; nt < 7; nt++) {
      atomicAdd(&norm2[n0 + nt * 8 + 2 * tig], ns0[nt]);
      atomicAdd(&norm2[n0 + nt * 8 + 2 * tig + 1], ns1[nt]);
    }
  }
  __syncthreads();
  // invn (overwrite norm2 slot with invn for the fused-K2 pass)
  if (tid < NCOLS) {
    int bs = (tid >= 112) ? 1 : 0;
    int t = tid - bs * 112;
    float iv = rsqrtf(norm2[tid]);
    norm2[tid] = iv;
    if (t < Tn) g_invn[(b0 + bs) * Tn + t] = iv;
  }
  __syncthreads();

  // ---- fused K2: sigma_b and u_b[c] = 2 x * sum_t m/n ----
  if (tid < 2) {
    float s = 0.0f;
    for (int t = 0; t < Tn; t++) s += norm2[tid * 112 + t];
    g_sigma[b0 + tid] = s;
  }
#pragma unroll
  for (int bs = 0; bs < 2; bs++) {
#pragma unroll
    for (int j = 0; j < 2; j++) {
      int c = tid + j * 256;
      int w = c >> 5, sh = c & 31;
      float s = 0.0f;
      for (int col = 0; col < 112; col++) {
        uint32_t mwv = maskS[(bs * 112 + col) * MPAD + w];
        if ((mwv >> sh) & 1u) s += norm2[bs * 112 + col];
      }
      g_u[(b0 + bs) * Cn + c] = 2.0f * x[(b0 + bs) * Cn + c] * s;
    }
  }
}

// K3h: fp16 tensor-core small GEMMs.
//   MODE 0: S = u * W^T + sigma*bias   A=g_u, B=g_Wh  (B[n][k] = W[n][k])
//   MODE 1: v = S * W                  A=g_S, B=g_WhT (B[n][k] = W[k][n])
template <int MODE>
__global__ __launch_bounds__(256) void k3h_gemm(const float* __restrict__ bias) {
  __shared__ __half As[64 * 72];
  __shared__ __half Bs[64 * 72];
  const float* A = (MODE == 0) ? g_u : g_S;
  const __half* Bsrc = (MODE == 0) ? g_Wh : g_WhT;
  float* outp = (MODE == 0) ? g_S : g_v;
  const int n0 = blockIdx.x * 64, m0 = blockIdx.y * 64;
  const int tid = threadIdx.x;
  const int lane = tid & 31, wid = tid >> 5;
  const int warp_m = wid & 3, warp_n = wid >> 2;   // 4 m-warps x 2 n-warps
  const int gID = lane >> 2, tig = lane & 3;

  float acc[4][4] = {};
  for (int k0 = 0; k0 < 512; k0 += 64) {
    __syncthreads();
    // stage A (fp32 -> fp16)
    for (int l = tid; l < 1024; l += 256) {
      int mm = l >> 4, kk4 = (l & 15) << 2;
      float4 v = *reinterpret_cast<const float4*>(A + (m0 + mm) * 512 + k0 + kk4);
      __half2 h0 = __floats2half2_rn(v.x, v.y);
      __half2 h1 = __floats2half2_rn(v.z, v.w);
      uint2 pk = make_uint2(*reinterpret_cast<uint32_t*>(&h0),
                            *reinterpret_cast<uint32_t*>(&h1));
      *reinterpret_cast<uint2*>(As + mm * 72 + kk4) = pk;
    }
    // stage B (fp16 direct, 16B chunks)
    for (int l = tid; l < 512; l += 256) {
      int nn = l >> 3, kk8 = (l & 7) << 3;
      *reinterpret_cast<uint4*>(Bs + nn * 72 + kk8) =
          *reinterpret_cast<const uint4*>(Bsrc + (n0 + nn) * 512 + k0 + kk8);
    }
    __syncthreads();
#pragma unroll
    for (int kt = 0; kt < 4; kt++) {
      const __half* ap = As + (warp_m * 16 + gID) * 72 + kt * 16 + tig * 2;
      uint32_t a0 = *reinterpret_cast<const uint32_t*>(ap);
      uint32_t a1 = *reinterpret_cast<const uint32_t*>(ap + 8 * 72);
      uint32_t a2 = *reinterpret_cast<const uint32_t*>(ap + 8);
      uint32_t a3 = *reinterpret_cast<const uint32_t*>(ap + 8 * 72 + 8);
#pragma unroll
      for (int nt = 0; nt < 4; nt++) {
        const __half* bp = Bs + (warp_n * 32 + nt * 8 + gID) * 72 + kt * 16 + tig * 2;
        uint32_t b0 = *reinterpret_cast<const uint32_t*>(bp);
        uint32_t b1 = *reinterpret_cast<const uint32_t*>(bp + 8);
        mma_f16(acc[nt], a0, a1, a2, a3, b0, b1);
      }
    }
  }
  // epilogue (fp32): rows m, m+8; cols n, n+1 per nt
  const int mr = m0 + warp_m * 16 + gID;
  float sg0 = (MODE == 0) ? g_sigma[mr] : 0.0f;
  float sg1 = (MODE == 0) ? g_sigma[mr + 8] : 0.0f;
#pragma unroll
  for (int nt = 0; nt < 4; nt++) {
    int n = n0 + warp_n * 32 + nt * 8 + tig * 2;
    float bb0 = (MODE == 0) ? bias[n] : 0.0f;
    float bb1 = (MODE == 0) ? bias[n + 1] : 0.0f;
    float2 lo = make_float2(acc[nt][0] + sg0 * bb0, acc[nt][1] + sg0 * bb1);
    float2 hi = make_float2(acc[nt][2] + sg1 * bb0, acc[nt][3] + sg1 * bb1);
    *reinterpret_cast<float2*>(outp + mr * 512 + n) = lo;
    *reinterpret_cast<float2*>(outp + (mr + 8) * 512 + n) = hi;
  }
}

// K3c: 1/|S_b| and b^T S_b
__global__ void k3c_reduce(const float* __restrict__ bias) {
  __shared__ float r1[128], r2[128];
  const int b = blockIdx.x, tid = threadIdx.x;  // 128
  float s1 = 0.0f, s2 = 0.0f;
  for (int d = tid; d < Dn; d += 128) {
    float v = g_S[b * Dn + d];
    s1 += v * v;
    s2 += bias[d] * v;
  }
  r1[tid] = s1; r2[tid] = s2;
  __syncthreads();
  for (int o = 64; o > 0; o >>= 1) {
    if (tid < o) { r1[tid] += r1[tid + o]; r2[tid] += r2[tid + o]; }
    __syncthreads();
  }
  if (tid == 0) { g_sinv[b] = rsqrtf(r1[0]); g_c0[b] = r2[0]; }
}

// K4: score_tb = (2 sum_c m*x*v + c0) * invn * sinv ; out = std over t (ddof=0)
__global__ void k4_scores(const float* __restrict__ x, float* __restrict__ out) {
  __shared__ float xv[Cn];
  __shared__ float sc[Tn];
  const int b = blockIdx.x, tid = threadIdx.x;  // 128
  for (int c = tid; c < Cn; c += 128)
    xv[c] = 2.0f * x[b * Cn + c] * g_v[b * Cn + c];
  __syncthreads();
  if (tid < Tn) {
    const int t = tid;
    const uint32_t* mw = &g_mask[(t * Bn + b) * NW];
    float s = 0.0f;
#pragma unroll
    for (int w = 0; w < NW; w++) {
      uint32_t m = mw[w];
      int base = w * 32;
#pragma unroll
      for (int k = 0; k < 32; k++)
        if (m & (1u << k)) s += xv[base + k];
    }
    sc[t] = (s + g_c0[b]) * g_invn[b * Tn + t] * g_sinv[b];
  }
  __syncthreads();
  if (tid == 0) {
    float m = 0.0f;
    for (int t = 0; t < Tn; t++) m += sc[t];
    m *= (1.0f / Tn);
    float v = 0.0f;
    for (int t = 0; t < Tn; t++) { float d = sc[t] - m; v += d * d; }
    v *= (1.0f / Tn);
    out[b] = sqrtf(v);
  }
}

#define K1_SMEM_BYTES (2 * WBUFH * 2 + 512 * 4 + NCOLS * MPAD * 4 + NCOLS * 4)

extern "C" void kernel_launch(void* const* d_in, const int* in_sizes, int n_in,
                              void* d_out, int out_size) {
  const float* x    = (const float*)d_in[0];
  const float* W    = (const float*)d_in[1];
  const float* bias = (const float*)d_in[2];
  float* out = (float*)d_out;

  cudaFuncSetAttribute(k1_norms_tc,
                       cudaFuncAttributeMaxDynamicSharedMemorySize,
                       K1_SMEM_BYTES);

  k0_masks<<<819200, 256>>>();                // Tn*Bn*Cn / 256 elements
  k0b_halfW<<<1024, 256>>>(W);                // fp16 W (+transpose) once
  k1_norms_tc<<<Bn / 2, 256, K1_SMEM_BYTES>>>(x, bias);
  k3h_gemm<0><<<dim3(8, 64), 256>>>(bias);    // S = u W^T + sigma b
  k3c_reduce<<<Bn, 128>>>(bias);              // |S|, b^T S
  k3h_gemm<1><<<dim3(8, 64), 256>>>(bias);    // v = S W
  k4_scores<<<Bn, 128>>>(x, out);
}